// round 6
// baseline (speedup 1.0000x reference)
#include <cuda_runtime.h>

#define N_NODES 100000
#define CIN 128
#define CHID 128
#define COUT 64

// ---------------- scratch ----------------
__device__ __align__(16) float g_sum1[(size_t)N_NODES * CIN];
__device__ __align__(16) float g_deg [N_NODES];
__device__ __align__(16) float g_h   [(size_t)N_NODES * CHID];
__device__ __align__(16) float g_t   [(size_t)N_NODES * COUT];
__device__ __align__(16) float g_r   [(size_t)N_NODES * COUT];
__device__ __align__(16) float g_sum2[(size_t)N_NODES * COUT];
__device__ int g_is64;

// ---------------- packed f32x2 helpers ----------------
__device__ __forceinline__ unsigned long long dupf2(float v) {
    unsigned long long r;
    asm("mov.b64 %0, {%1, %1};" : "=l"(r) : "r"(__float_as_uint(v)));
    return r;
}
__device__ __forceinline__ void fma2(unsigned long long& d,
                                     unsigned long long a, unsigned long long b) {
    asm("fma.rn.f32x2 %0, %1, %2, %0;" : "+l"(d) : "l"(a), "l"(b));
}
__device__ __forceinline__ void unpack2(unsigned long long p, float& lo, float& hi) {
    unsigned int l, h;
    asm("mov.b64 {%0, %1}, %2;" : "=r"(l), "=r"(h) : "l"(p));
    lo = __uint_as_float(l); hi = __uint_as_float(h);
}

// ---------------- zero + flag ----------------
__global__ void zero_kernel() {
    long long i = (long long)blockIdx.x * blockDim.x + threadIdx.x;
    const long long s1 = (long long)(N_NODES * (CIN / 4));
    const long long s2 = (long long)(N_NODES * (COUT / 4));
    float4 z = {0.f, 0.f, 0.f, 0.f};
    if (i < s1) reinterpret_cast<float4*>(g_sum1)[i] = z;
    if (i < s2) reinterpret_cast<float4*>(g_sum2)[i] = z;
    if (i < N_NODES) g_deg[i] = 0.f;
    if (i == 0) g_is64 = 1;
}

// ---------------- detect edge_index dtype ----------------
__global__ void detect_kernel(const long long* __restrict__ ei, long long n) {
    long long i = (long long)blockIdx.x * blockDim.x + threadIdx.x;
    long long stride = (long long)gridDim.x * blockDim.x;
    for (; i < n; i += stride) {
        unsigned long long v = (unsigned long long)ei[i];
        if (v >= (unsigned long long)N_NODES) { g_is64 = 0; return; }
    }
}

// ---------------- edge aggregation, layer 1 ----------------
__global__ void edge_agg1(const float* __restrict__ x,
                          const void* __restrict__ ei_raw, int E) {
    int e    = (blockIdx.x * blockDim.x + threadIdx.x) >> 5;
    int lane = threadIdx.x & 31;
    if (e >= E) return;
    int src, dst;
    if (g_is64) {
        const long long* ei = (const long long*)ei_raw;
        src = (int)ei[e]; dst = (int)ei[(size_t)E + e];
    } else {
        const int* ei = (const int*)ei_raw;
        src = ei[e]; dst = ei[(size_t)E + e];
    }
    if ((unsigned)src >= N_NODES || (unsigned)dst >= N_NODES) return;
    float4 v = *reinterpret_cast<const float4*>(x + (size_t)src * CIN + lane * 4);
    float* d = g_sum1 + (size_t)dst * CIN + lane * 4;
    asm volatile("red.global.add.v4.f32 [%0], {%1, %2, %3, %4};"
                 :: "l"(d), "f"(v.x), "f"(v.y), "f"(v.z), "f"(v.w) : "memory");
    if (lane == 0) atomicAdd(g_deg + dst, 1.0f);
}

// ---------------- edge aggregation, layer 2 ----------------
__global__ void edge_agg2(const void* __restrict__ ei_raw, int E) {
    int idx = blockIdx.x * blockDim.x + threadIdx.x;
    int e   = idx >> 4;
    int l   = idx & 15;
    if (e >= E) return;
    int src, dst;
    if (g_is64) {
        const long long* ei = (const long long*)ei_raw;
        src = (int)ei[e]; dst = (int)ei[(size_t)E + e];
    } else {
        const int* ei = (const int*)ei_raw;
        src = ei[e]; dst = ei[(size_t)E + e];
    }
    if ((unsigned)src >= N_NODES || (unsigned)dst >= N_NODES) return;
    float4 v = *reinterpret_cast<const float4*>(g_t + (size_t)src * COUT + l * 4);
    float* d = g_sum2 + (size_t)dst * COUT + l * 4;
    asm volatile("red.global.add.v4.f32 [%0], {%1, %2, %3, %4};"
                 :: "l"(d), "f"(v.x), "f"(v.y), "f"(v.z), "f"(v.w) : "memory");
}

// ================= GEMM common shape =================
// BM=64, BN=128, BK=32, 256 threads (8 warps), 2 CTAs/SM.
// Warp tile: 32 rows x 32 cols. Thread: 1 row x 32 cols = 16 f32x2 col-pairs.
// Per k/thread: 1 LDS.32 (A, conflict-free) + 1 dup + 16 u64 broadcast W reads.
#define APITCH 65

// ---------------- GEMM layer 1 ----------------
// h = relu([mean | x] @ [W1l ; W1r] + b1)   A:[N,256]  W:[256,128]
__global__ void __launch_bounds__(256, 2) gemm1(const float* __restrict__ x,
                                                const float* __restrict__ W1l,
                                                const float* __restrict__ W1r,
                                                const float* __restrict__ b1) {
    __shared__ __align__(16) float Ws[32 * 128];
    __shared__ __align__(16) float As[32 * APITCH];

    const int tid = threadIdx.x;
    const int block_m = blockIdx.x * 64;

    // A loader: node lm = tid>>2 (0..63), 8 k at lk0 = (tid&3)*8
    const int lm   = tid >> 2;
    const int lk0  = (tid & 3) * 8;
    const int lnode = block_m + lm;
    const bool lvalid = (lnode < N_NODES);
    float rdeg = 1.0f;
    if (lvalid) rdeg = 1.0f / fmaxf(g_deg[lnode], 1.0f);

    // compute mapping
    const int lane = tid & 31;
    const int warp = tid >> 5;
    const int m0 = (warp & 1) * 32;      // row group
    const int c0 = (warp >> 1) * 32;     // col group (32 cols = 16 pairs)
    const int row = m0 + lane;           // 0..63

    unsigned long long acc[16];
#pragma unroll
    for (int j = 0; j < 16; j++) acc[j] = 0ull;

    float4 av[2];   // 8 A values
    float4 wv[4];   // 16 W values

    auto load_chunk = [&](int ch) {
        const int kbase = ch * 32;
        if (lvalid) {
            if (kbase < 128) {
                const float4* p = reinterpret_cast<const float4*>(
                    g_sum1 + (size_t)lnode * CIN + kbase + lk0);
                float4 t0 = p[0], t1 = p[1];
                av[0] = make_float4(t0.x * rdeg, t0.y * rdeg, t0.z * rdeg, t0.w * rdeg);
                av[1] = make_float4(t1.x * rdeg, t1.y * rdeg, t1.z * rdeg, t1.w * rdeg);
            } else {
                const float4* p = reinterpret_cast<const float4*>(
                    x + (size_t)lnode * CIN + (kbase - 128) + lk0);
                av[0] = p[0]; av[1] = p[1];
            }
        } else {
            av[0] = av[1] = make_float4(0.f, 0.f, 0.f, 0.f);
        }
#pragma unroll
        for (int i = 0; i < 4; i++) {
            int fidx = tid + i * 256;
            int kk = fidx >> 5, j4 = fidx & 31;
            int k = kbase + kk;
            const float* wrow = (k < 128) ? (W1l + k * 128) : (W1r + (k - 128) * 128);
            wv[i] = *reinterpret_cast<const float4*>(wrow + j4 * 4);
        }
    };
    auto store_chunk = [&]() {
        float t0[4] = {av[0].x, av[0].y, av[0].z, av[0].w};
        float t1[4] = {av[1].x, av[1].y, av[1].z, av[1].w};
#pragma unroll
        for (int j = 0; j < 4; j++) {
            As[(lk0 + j) * APITCH + lm] = t0[j];
            As[(lk0 + 4 + j) * APITCH + lm] = t1[j];
        }
#pragma unroll
        for (int i = 0; i < 4; i++) {
            int fidx = tid + i * 256;
            int kk = fidx >> 5, j4 = fidx & 31;
            *reinterpret_cast<float4*>(&Ws[kk * 128 + j4 * 4]) = wv[i];
        }
    };

    load_chunk(0);
    for (int ch = 0; ch < 8; ch++) {
        store_chunk();
        __syncthreads();
        if (ch + 1 < 8) load_chunk(ch + 1);

#pragma unroll 4
        for (int kk = 0; kk < 32; kk++) {
            unsigned long long ad = dupf2(As[kk * APITCH + row]);
            const unsigned long long* wp =
                reinterpret_cast<const unsigned long long*>(&Ws[kk * 128 + c0]);
#pragma unroll
            for (int j = 0; j < 16; j++) fma2(acc[j], ad, wp[j]);
        }
        __syncthreads();
    }

    const int n = block_m + row;
    if (n < N_NODES) {
        float o[32];
#pragma unroll
        for (int j = 0; j < 16; j++) unpack2(acc[j], o[2 * j], o[2 * j + 1]);
#pragma unroll
        for (int j = 0; j < 32; j++) o[j] = fmaxf(o[j] + b1[c0 + j], 0.f);
        float4* dst = reinterpret_cast<float4*>(g_h + (size_t)n * CHID + c0);
#pragma unroll
        for (int q = 0; q < 8; q++)
            dst[q] = make_float4(o[4 * q], o[4 * q + 1], o[4 * q + 2], o[4 * q + 3]);
    }
}

// ---------------- GEMM layer 2 ----------------
// [t | r] = h @ [W2l | W2r] (+ [0 | b2])   A:[N,128]  W:[128,128]
__global__ void __launch_bounds__(256, 2) gemm2(const float* __restrict__ W2l,
                                                const float* __restrict__ W2r,
                                                const float* __restrict__ b2) {
    __shared__ __align__(16) float Ws[32 * 128];
    __shared__ __align__(16) float As[32 * APITCH];

    const int tid = threadIdx.x;
    const int block_m = blockIdx.x * 64;

    const int lm   = tid >> 2;
    const int lk0  = (tid & 3) * 8;
    const int lnode = block_m + lm;
    const bool lvalid = (lnode < N_NODES);

    const int lane = tid & 31;
    const int warp = tid >> 5;
    const int m0 = (warp & 1) * 32;
    const int c0 = (warp >> 1) * 32;
    const int row = m0 + lane;

    unsigned long long acc[16];
#pragma unroll
    for (int j = 0; j < 16; j++) acc[j] = 0ull;

    float4 av[2];
    float4 wv[4];

    auto load_chunk = [&](int ch) {
        const int kbase = ch * 32;
        if (lvalid) {
            const float4* p = reinterpret_cast<const float4*>(
                g_h + (size_t)lnode * CHID + kbase + lk0);
            av[0] = p[0]; av[1] = p[1];
        } else {
            av[0] = av[1] = make_float4(0.f, 0.f, 0.f, 0.f);
        }
#pragma unroll
        for (int i = 0; i < 4; i++) {
            int fidx = tid + i * 256;
            int kk = fidx >> 5, j4 = fidx & 31;
            int k = kbase + kk;
            const float* wrow = (j4 < 16) ? (W2l + k * 64 + j4 * 4)
                                          : (W2r + k * 64 + (j4 - 16) * 4);
            wv[i] = *reinterpret_cast<const float4*>(wrow);
        }
    };
    auto store_chunk = [&]() {
        float t0[4] = {av[0].x, av[0].y, av[0].z, av[0].w};
        float t1[4] = {av[1].x, av[1].y, av[1].z, av[1].w};
#pragma unroll
        for (int j = 0; j < 4; j++) {
            As[(lk0 + j) * APITCH + lm] = t0[j];
            As[(lk0 + 4 + j) * APITCH + lm] = t1[j];
        }
#pragma unroll
        for (int i = 0; i < 4; i++) {
            int fidx = tid + i * 256;
            int kk = fidx >> 5, j4 = fidx & 31;
            *reinterpret_cast<float4*>(&Ws[kk * 128 + j4 * 4]) = wv[i];
        }
    };

    load_chunk(0);
    for (int ch = 0; ch < 4; ch++) {
        store_chunk();
        __syncthreads();
        if (ch + 1 < 4) load_chunk(ch + 1);

#pragma unroll 4
        for (int kk = 0; kk < 32; kk++) {
            unsigned long long ad = dupf2(As[kk * APITCH + row]);
            const unsigned long long* wp =
                reinterpret_cast<const unsigned long long*>(&Ws[kk * 128 + c0]);
#pragma unroll
            for (int j = 0; j < 16; j++) fma2(acc[j], ad, wp[j]);
        }
        __syncthreads();
    }

    const int n = block_m + row;
    if (n < N_NODES) {
        float o[32];
#pragma unroll
        for (int j = 0; j < 16; j++) unpack2(acc[j], o[2 * j], o[2 * j + 1]);
        if (c0 < 64) {
            // cols [0,64): t = h @ W2l (no bias)
            float4* dst = reinterpret_cast<float4*>(g_t + (size_t)n * COUT + c0);
#pragma unroll
            for (int q = 0; q < 8; q++)
                dst[q] = make_float4(o[4 * q], o[4 * q + 1], o[4 * q + 2], o[4 * q + 3]);
        } else {
            const int cc = c0 - 64;
#pragma unroll
            for (int j = 0; j < 32; j++) o[j] += b2[cc + j];
            float4* dst = reinterpret_cast<float4*>(g_r + (size_t)n * COUT + cc);
#pragma unroll
            for (int q = 0; q < 8; q++)
                dst[q] = make_float4(o[4 * q], o[4 * q + 1], o[4 * q + 2], o[4 * q + 3]);
        }
    }
}

// ---------------- final: out = sum2/clip(deg,1) + r ----------------
__global__ void final_kernel(float* __restrict__ out) {
    int i = blockIdx.x * blockDim.x + threadIdx.x;
    if (i >= N_NODES * (COUT / 4)) return;
    int n = i >> 4;
    float rd = 1.0f / fmaxf(g_deg[n], 1.0f);
    float4 s = reinterpret_cast<const float4*>(g_sum2)[i];
    float4 r = reinterpret_cast<const float4*>(g_r)[i];
    float4 o = {s.x * rd + r.x, s.y * rd + r.y, s.z * rd + r.z, s.w * rd + r.w};
    reinterpret_cast<float4*>(out)[i] = o;
}

// ---------------- launch ----------------
extern "C" void kernel_launch(void* const* d_in, const int* in_sizes, int n_in,
                              void* d_out, int out_size) {
    const float* x   = (const float*)d_in[0];
    const void*  ei  = d_in[1];
    const float* W1l = (const float*)d_in[2];
    const float* W1r = (const float*)d_in[3];
    const float* b1  = (const float*)d_in[4];
    const float* W2l = (const float*)d_in[5];
    const float* W2r = (const float*)d_in[6];
    const float* b2  = (const float*)d_in[7];
    float* out = (float*)d_out;

    const int E = in_sizes[1] / 2;

    {
        long long tot = (long long)N_NODES * (CIN / 4);
        int blocks = (int)((tot + 255) / 256);
        zero_kernel<<<blocks, 256>>>();
    }
    {
        long long n64_safe = (long long)E / 2;
        detect_kernel<<<1024, 256>>>((const long long*)ei, n64_safe);
    }
    {
        long long threads = (long long)E * 32;
        int blocks = (int)((threads + 255) / 256);
        edge_agg1<<<blocks, 256>>>(x, ei, E);
    }
    {
        int blocks = (N_NODES + 63) / 64;
        gemm1<<<blocks, 256>>>(x, W1l, W1r, b1);
        gemm2<<<blocks, 256>>>(W2l, W2r, b2);
    }
    {
        long long threads = (long long)E * 16;
        int blocks = (int)((threads + 255) / 256);
        edge_agg2<<<blocks, 256>>>(ei, E);
    }
    {
        int blocks = (N_NODES * (COUT / 4) + 255) / 256;
        final_kernel<<<blocks, 256>>>(out);
    }
}

// round 7
// speedup vs baseline: 1.2577x; 1.2577x over previous
#include <cuda_runtime.h>

#define N_NODES 100000
#define CIN 128
#define CHID 128
#define COUT 64
#define MAXE 1600000

// ---------------- scratch ----------------
__device__ __align__(16) float g_mean1[(size_t)N_NODES * CIN];   // mean of x over in-edges
__device__ __align__(16) float g_h    [(size_t)N_NODES * CHID];  // relu(layer1)
__device__ __align__(16) float g_t    [(size_t)N_NODES * COUT];  // h @ W2l
__device__ __align__(16) float g_r    [(size_t)N_NODES * COUT];  // h @ W2r + b2
__device__ int g_degi  [N_NODES];
__device__ int g_row   [N_NODES + 1];
__device__ int g_cursor[N_NODES];
__device__ int g_srcbuf[MAXE];
__device__ int g_dstbuf[MAXE];
__device__ int g_csr   [MAXE];
__device__ int g_is64;

// ---------------- packed f32x2 helpers ----------------
__device__ __forceinline__ unsigned long long dupf2(float v) {
    unsigned long long r;
    asm("mov.b64 %0, {%1, %1};" : "=l"(r) : "r"(__float_as_uint(v)));
    return r;
}
__device__ __forceinline__ void fma2(unsigned long long& d,
                                     unsigned long long a, unsigned long long b) {
    asm("fma.rn.f32x2 %0, %1, %2, %0;" : "+l"(d) : "l"(a), "l"(b));
}
__device__ __forceinline__ void unpack2(unsigned long long p, float& lo, float& hi) {
    unsigned int l, h;
    asm("mov.b64 {%0, %1}, %2;" : "=r"(l), "=r"(h) : "l"(p));
    lo = __uint_as_float(l); hi = __uint_as_float(h);
}

// ---------------- zero deg + init flag ----------------
__global__ void zero_deg() {
    int i = blockIdx.x * blockDim.x + threadIdx.x;
    if (i < N_NODES) g_degi[i] = 0;
    if (i == 0) g_is64 = 1;
}

// ---------------- detect edge_index dtype ----------------
__global__ void detect_kernel(const long long* __restrict__ ei, long long n) {
    long long i = (long long)blockIdx.x * blockDim.x + threadIdx.x;
    long long stride = (long long)gridDim.x * blockDim.x;
    for (; i < n; i += stride) {
        unsigned long long v = (unsigned long long)ei[i];
        if (v >= (unsigned long long)N_NODES) { g_is64 = 0; return; }
    }
}

// ---------------- decode edges + degree histogram ----------------
__global__ void decode_count(const void* __restrict__ ei_raw, int E) {
    int e = blockIdx.x * blockDim.x + threadIdx.x;
    if (e >= E) return;
    int src, dst;
    if (g_is64) {
        const long long* ei = (const long long*)ei_raw;
        src = (int)ei[e]; dst = (int)ei[(size_t)E + e];
    } else {
        const int* ei = (const int*)ei_raw;
        src = ei[e]; dst = ei[(size_t)E + e];
    }
    if ((unsigned)src >= N_NODES) src = 0;
    if ((unsigned)dst >= N_NODES) dst = 0;
    g_srcbuf[e] = src;
    g_dstbuf[e] = dst;
    atomicAdd(&g_degi[dst], 1);
}

// ---------------- prefix sum over degrees (1 block) ----------------
__global__ void scan_kernel() {
    __shared__ int sp[1024];
    const int tid = threadIdx.x;
    const int chunk = (N_NODES + 1023) / 1024;   // 98
    const int start = tid * chunk;
    const int end   = min(start + chunk, N_NODES);
    int s = 0;
    for (int i = start; i < end; i++) s += g_degi[i];
    sp[tid] = s;
    __syncthreads();
    // Hillis-Steele inclusive scan
    for (int off = 1; off < 1024; off <<= 1) {
        int v = (tid >= off) ? sp[tid - off] : 0;
        __syncthreads();
        sp[tid] += v;
        __syncthreads();
    }
    int run = sp[tid] - s;   // exclusive prefix for this thread's chunk
    for (int i = start; i < end; i++) {
        g_row[i] = run;
        g_cursor[i] = run;
        run += g_degi[i];
    }
    if (tid == 0) g_row[N_NODES] = sp[1023];
}

// ---------------- scatter edges into CSR ----------------
__global__ void scatter_kernel(int E) {
    int e = blockIdx.x * blockDim.x + threadIdx.x;
    if (e >= E) return;
    int dst = g_dstbuf[e];
    int pos = atomicAdd(&g_cursor[dst], 1);
    if (pos < MAXE) g_csr[pos] = g_srcbuf[e];
}

// ---------------- agg layer 1: mean of x over in-neighbors (CSR) ----------------
__global__ void agg1_csr(const float* __restrict__ x) {
    int w    = (blockIdx.x * blockDim.x + threadIdx.x) >> 5;
    int lane = threadIdx.x & 31;
    if (w >= N_NODES) return;
    const int beg = g_row[w], end = g_row[w + 1];
    float4 a0 = {0.f, 0.f, 0.f, 0.f}, a1 = {0.f, 0.f, 0.f, 0.f};
    int i = beg;
    for (; i + 1 < end; i += 2) {
        int s0 = g_csr[i], s1 = g_csr[i + 1];
        float4 v0 = *reinterpret_cast<const float4*>(x + (size_t)s0 * CIN + lane * 4);
        float4 v1 = *reinterpret_cast<const float4*>(x + (size_t)s1 * CIN + lane * 4);
        a0.x += v0.x; a0.y += v0.y; a0.z += v0.z; a0.w += v0.w;
        a1.x += v1.x; a1.y += v1.y; a1.z += v1.z; a1.w += v1.w;
    }
    if (i < end) {
        int s0 = g_csr[i];
        float4 v0 = *reinterpret_cast<const float4*>(x + (size_t)s0 * CIN + lane * 4);
        a0.x += v0.x; a0.y += v0.y; a0.z += v0.z; a0.w += v0.w;
    }
    float rd = 1.0f / fmaxf((float)(end - beg), 1.0f);
    float4 o = {(a0.x + a1.x) * rd, (a0.y + a1.y) * rd,
                (a0.z + a1.z) * rd, (a0.w + a1.w) * rd};
    *reinterpret_cast<float4*>(g_mean1 + (size_t)w * CIN + lane * 4) = o;
}

// ---------------- agg layer 2 + final: out = mean(t) + r ----------------
__global__ void agg2_final(float* __restrict__ out) {
    int w    = (blockIdx.x * blockDim.x + threadIdx.x) >> 5;
    int lane = threadIdx.x & 31;
    if (w >= N_NODES) return;
    const int beg = g_row[w], end = g_row[w + 1];
    float2 a0 = {0.f, 0.f}, a1 = {0.f, 0.f};
    int i = beg;
    for (; i + 1 < end; i += 2) {
        int s0 = g_csr[i], s1 = g_csr[i + 1];
        float2 v0 = *reinterpret_cast<const float2*>(g_t + (size_t)s0 * COUT + lane * 2);
        float2 v1 = *reinterpret_cast<const float2*>(g_t + (size_t)s1 * COUT + lane * 2);
        a0.x += v0.x; a0.y += v0.y;
        a1.x += v1.x; a1.y += v1.y;
    }
    if (i < end) {
        int s0 = g_csr[i];
        float2 v0 = *reinterpret_cast<const float2*>(g_t + (size_t)s0 * COUT + lane * 2);
        a0.x += v0.x; a0.y += v0.y;
    }
    float rd = 1.0f / fmaxf((float)(end - beg), 1.0f);
    float2 r = *reinterpret_cast<const float2*>(g_r + (size_t)w * COUT + lane * 2);
    float2 o = {(a0.x + a1.x) * rd + r.x, (a0.y + a1.y) * rd + r.y};
    *reinterpret_cast<float2*>(out + (size_t)w * COUT + lane * 2) = o;
}

// ================= GEMMs: exact round-4 shape (known 170/85 µs) =================
// BM=64, BN=128, BK=32, 256 threads; per thread 8 rows x 4 cols as 4x4 f32x2.
#define APITCH 66

// ---------------- GEMM layer 1 ----------------
// h = relu([mean1 | x] @ [W1l ; W1r] + b1)   A:[N,256]  W:[256,128]
__global__ void __launch_bounds__(256) gemm1(const float* __restrict__ x,
                                             const float* __restrict__ W1l,
                                             const float* __restrict__ W1r,
                                             const float* __restrict__ b1) {
    __shared__ __align__(16) float Ws[32 * 128];
    __shared__ __align__(16) float As[32 * APITCH];

    const int tid = threadIdx.x;
    const int block_m = blockIdx.x * 64;

    const int lm   = tid >> 2;
    const int lk0  = (tid & 3) * 8;
    const int node = block_m + lm;
    const bool valid = (node < N_NODES);

    const int c0 = (tid & 31) * 4;
    const int r0 = (tid >> 5) * 8;

    unsigned long long acc[4][4];
#pragma unroll
    for (int c = 0; c < 4; c++)
#pragma unroll
        for (int p = 0; p < 4; p++) acc[c][p] = 0ull;

    for (int ch = 0; ch < 8; ch++) {
        const int kbase = ch * 32;

#pragma unroll
        for (int i = 0; i < 16; i++) {
            int idx = tid + i * 256;
            int kk = idx >> 7, j = idx & 127;
            int k = kbase + kk;
            Ws[idx] = (k < 128) ? W1l[k * 128 + j] : W1r[(k - 128) * 128 + j];
        }

        float av[8];
        if (valid) {
            const float* p = (kbase < 128)
                ? (g_mean1 + (size_t)node * CIN + kbase + lk0)
                : (x + (size_t)node * CIN + (kbase - 128) + lk0);
#pragma unroll
            for (int j = 0; j < 8; j++) av[j] = p[j];
        } else {
#pragma unroll
            for (int j = 0; j < 8; j++) av[j] = 0.f;
        }
        __syncthreads();
#pragma unroll
        for (int j = 0; j < 8; j++) As[(lk0 + j) * APITCH + lm] = av[j];
        __syncthreads();

#pragma unroll
        for (int kk = 0; kk < 32; kk++) {
            float4 w = *reinterpret_cast<const float4*>(&Ws[kk * 128 + c0]);
            unsigned long long wd[4];
            wd[0] = dupf2(w.x); wd[1] = dupf2(w.y);
            wd[2] = dupf2(w.z); wd[3] = dupf2(w.w);
            const unsigned long long* ap =
                reinterpret_cast<const unsigned long long*>(&As[kk * APITCH + r0]);
            unsigned long long a01 = ap[0], a23 = ap[1], a45 = ap[2], a67 = ap[3];
#pragma unroll
            for (int c = 0; c < 4; c++) {
                fma2(acc[c][0], wd[c], a01);
                fma2(acc[c][1], wd[c], a23);
                fma2(acc[c][2], wd[c], a45);
                fma2(acc[c][3], wd[c], a67);
            }
        }
        __syncthreads();
    }

    float bv[4] = {b1[c0], b1[c0 + 1], b1[c0 + 2], b1[c0 + 3]};
    float res[8][4];
#pragma unroll
    for (int c = 0; c < 4; c++)
#pragma unroll
        for (int p = 0; p < 4; p++)
            unpack2(acc[c][p], res[2 * p][c], res[2 * p + 1][c]);
#pragma unroll
    for (int r = 0; r < 8; r++) {
        int n = block_m + r0 + r;
        if (n < N_NODES) {
            float4 o;
            o.x = fmaxf(res[r][0] + bv[0], 0.f);
            o.y = fmaxf(res[r][1] + bv[1], 0.f);
            o.z = fmaxf(res[r][2] + bv[2], 0.f);
            o.w = fmaxf(res[r][3] + bv[3], 0.f);
            *reinterpret_cast<float4*>(g_h + (size_t)n * CHID + c0) = o;
        }
    }
}

// ---------------- GEMM layer 2 ----------------
// [t | r] = h @ [W2l | W2r] (+ [0 | b2])   A:[N,128]  W:[128,128]
__global__ void __launch_bounds__(256) gemm2(const float* __restrict__ W2l,
                                             const float* __restrict__ W2r,
                                             const float* __restrict__ b2) {
    __shared__ __align__(16) float Ws[32 * 128];
    __shared__ __align__(16) float As[32 * APITCH];

    const int tid = threadIdx.x;
    const int block_m = blockIdx.x * 64;

    const int lm   = tid >> 2;
    const int lk0  = (tid & 3) * 8;
    const int node = block_m + lm;
    const bool valid = (node < N_NODES);

    const int c0 = (tid & 31) * 4;
    const int r0 = (tid >> 5) * 8;

    unsigned long long acc[4][4];
#pragma unroll
    for (int c = 0; c < 4; c++)
#pragma unroll
        for (int p = 0; p < 4; p++) acc[c][p] = 0ull;

    for (int ch = 0; ch < 4; ch++) {
        const int kbase = ch * 32;

#pragma unroll
        for (int i = 0; i < 16; i++) {
            int idx = tid + i * 256;
            int kk = idx >> 7, j = idx & 127;
            int k = kbase + kk;
            Ws[idx] = (j < 64) ? W2l[k * 64 + j] : W2r[k * 64 + (j - 64)];
        }

        float av[8];
        if (valid) {
            const float* p = g_h + (size_t)node * CHID + kbase + lk0;
#pragma unroll
            for (int j = 0; j < 8; j++) av[j] = p[j];
        } else {
#pragma unroll
            for (int j = 0; j < 8; j++) av[j] = 0.f;
        }
        __syncthreads();
#pragma unroll
        for (int j = 0; j < 8; j++) As[(lk0 + j) * APITCH + lm] = av[j];
        __syncthreads();

#pragma unroll
        for (int kk = 0; kk < 32; kk++) {
            float4 w = *reinterpret_cast<const float4*>(&Ws[kk * 128 + c0]);
            unsigned long long wd[4];
            wd[0] = dupf2(w.x); wd[1] = dupf2(w.y);
            wd[2] = dupf2(w.z); wd[3] = dupf2(w.w);
            const unsigned long long* ap =
                reinterpret_cast<const unsigned long long*>(&As[kk * APITCH + r0]);
            unsigned long long a01 = ap[0], a23 = ap[1], a45 = ap[2], a67 = ap[3];
#pragma unroll
            for (int c = 0; c < 4; c++) {
                fma2(acc[c][0], wd[c], a01);
                fma2(acc[c][1], wd[c], a23);
                fma2(acc[c][2], wd[c], a45);
                fma2(acc[c][3], wd[c], a67);
            }
        }
        __syncthreads();
    }

    float res[8][4];
#pragma unroll
    for (int c = 0; c < 4; c++)
#pragma unroll
        for (int p = 0; p < 4; p++)
            unpack2(acc[c][p], res[2 * p][c], res[2 * p + 1][c]);

    if (c0 < 64) {
#pragma unroll
        for (int r = 0; r < 8; r++) {
            int n = block_m + r0 + r;
            if (n < N_NODES) {
                float4 o = {res[r][0], res[r][1], res[r][2], res[r][3]};
                *reinterpret_cast<float4*>(g_t + (size_t)n * COUT + c0) = o;
            }
        }
    } else {
        int cc = c0 - 64;
        float bv[4] = {b2[cc], b2[cc + 1], b2[cc + 2], b2[cc + 3]};
#pragma unroll
        for (int r = 0; r < 8; r++) {
            int n = block_m + r0 + r;
            if (n < N_NODES) {
                float4 o = {res[r][0] + bv[0], res[r][1] + bv[1],
                            res[r][2] + bv[2], res[r][3] + bv[3]};
                *reinterpret_cast<float4*>(g_r + (size_t)n * COUT + cc) = o;
            }
        }
    }
}

// ---------------- launch ----------------
extern "C" void kernel_launch(void* const* d_in, const int* in_sizes, int n_in,
                              void* d_out, int out_size) {
    const float* x   = (const float*)d_in[0];
    const void*  ei  = d_in[1];
    const float* W1l = (const float*)d_in[2];
    const float* W1r = (const float*)d_in[3];
    const float* b1  = (const float*)d_in[4];
    const float* W2l = (const float*)d_in[5];
    const float* W2r = (const float*)d_in[6];
    const float* b2  = (const float*)d_in[7];
    float* out = (float*)d_out;

    const int E = in_sizes[1] / 2;

    {
        int blocks = (N_NODES + 255) / 256;
        zero_deg<<<blocks, 256>>>();
    }
    {
        long long n64_safe = (long long)E / 2;   // in-bounds for both dtypes
        detect_kernel<<<1024, 256>>>((const long long*)ei, n64_safe);
    }
    {
        int blocks = (E + 255) / 256;
        decode_count<<<blocks, 256>>>(ei, E);
        scan_kernel<<<1, 1024>>>();
        scatter_kernel<<<blocks, 256>>>(E);
    }
    {
        long long threads = (long long)N_NODES * 32;
        int blocks = (int)((threads + 255) / 256);
        agg1_csr<<<blocks, 256>>>(x);
    }
    {
        int blocks = (N_NODES + 63) / 64;
        gemm1<<<blocks, 256>>>(x, W1l, W1r, b1);
        gemm2<<<blocks, 256>>>(W2l, W2r, b2);
    }
    {
        long long threads = (long long)N_NODES * 32;
        int blocks = (int)((threads + 255) / 256);
        agg2_final<<<blocks, 256>>>(out);
    }
}

// round 8
// speedup vs baseline: 1.7454x; 1.3877x over previous
#include <cuda_runtime.h>

#define N_NODES 100000
#define CIN 128
#define CHID 128
#define COUT 64
#define MAXE 1600000
#define SCAN_BLOCKS ((N_NODES + 255) / 256)   // 391

// ---------------- scratch ----------------
__device__ __align__(16) float g_mean1[(size_t)N_NODES * CIN];   // mean of x over in-edges
__device__ __align__(16) float g_h    [(size_t)N_NODES * CHID];  // relu(layer1)
__device__ __align__(16) float g_t    [(size_t)N_NODES * COUT];  // h @ W2l
__device__ __align__(16) float g_r    [(size_t)N_NODES * COUT];  // h @ W2r + b2
__device__ int g_degi  [N_NODES];
__device__ int g_row   [N_NODES + 1];
__device__ int g_cursor[N_NODES];
__device__ int g_srcbuf[MAXE];
__device__ int g_dstbuf[MAXE];
__device__ int g_csr   [MAXE];
__device__ int g_bsum  [512];
__device__ int g_is64;

// ---------------- packed f32x2 helpers ----------------
__device__ __forceinline__ unsigned long long dupf2(float v) {
    unsigned long long r;
    asm("mov.b64 %0, {%1, %1};" : "=l"(r) : "r"(__float_as_uint(v)));
    return r;
}
__device__ __forceinline__ void fma2(unsigned long long& d,
                                     unsigned long long a, unsigned long long b) {
    asm("fma.rn.f32x2 %0, %1, %2, %0;" : "+l"(d) : "l"(a), "l"(b));
}
__device__ __forceinline__ void unpack2(unsigned long long p, float& lo, float& hi) {
    unsigned int l, h;
    asm("mov.b64 {%0, %1}, %2;" : "=r"(l), "=r"(h) : "l"(p));
    lo = __uint_as_float(l); hi = __uint_as_float(h);
}

// ---------------- zero deg + init flag ----------------
__global__ void zero_deg() {
    int i = blockIdx.x * blockDim.x + threadIdx.x;
    if (i < N_NODES) g_degi[i] = 0;
    if (i == 0) g_is64 = 1;
}

// ---------------- detect edge_index dtype ----------------
__global__ void detect_kernel(const long long* __restrict__ ei, long long n) {
    long long i = (long long)blockIdx.x * blockDim.x + threadIdx.x;
    long long stride = (long long)gridDim.x * blockDim.x;
    for (; i < n; i += stride) {
        unsigned long long v = (unsigned long long)ei[i];
        if (v >= (unsigned long long)N_NODES) { g_is64 = 0; return; }
    }
}

// ---------------- decode edges + degree histogram ----------------
__global__ void decode_count(const void* __restrict__ ei_raw, int E) {
    int e = blockIdx.x * blockDim.x + threadIdx.x;
    if (e >= E) return;
    int src, dst;
    if (g_is64) {
        const long long* ei = (const long long*)ei_raw;
        src = (int)ei[e]; dst = (int)ei[(size_t)E + e];
    } else {
        const int* ei = (const int*)ei_raw;
        src = ei[e]; dst = ei[(size_t)E + e];
    }
    if ((unsigned)src >= N_NODES) src = 0;
    if ((unsigned)dst >= N_NODES) dst = 0;
    g_srcbuf[e] = src;
    g_dstbuf[e] = dst;
    atomicAdd(&g_degi[dst], 1);
}

// ---------------- scan phase A: per-block sums ----------------
__global__ void block_sum_kernel() {
    int i = blockIdx.x * 256 + threadIdx.x;
    int v = (i < N_NODES) ? g_degi[i] : 0;
#pragma unroll
    for (int o = 16; o; o >>= 1) v += __shfl_down_sync(0xffffffffu, v, o);
    __shared__ int ws[8];
    if ((threadIdx.x & 31) == 0) ws[threadIdx.x >> 5] = v;
    __syncthreads();
    if (threadIdx.x < 8) {
        int s = ws[threadIdx.x];
#pragma unroll
        for (int o = 4; o; o >>= 1) s += __shfl_down_sync(0xffu, s, o);
        if (threadIdx.x == 0) g_bsum[blockIdx.x] = s;
    }
}

// ---------------- scan phase B: scan block sums (1 block of 512) ----------------
__global__ void scan_bsum_kernel() {
    __shared__ int sp[512];
    int tid = threadIdx.x;
    int v = (tid < SCAN_BLOCKS) ? g_bsum[tid] : 0;
    sp[tid] = v;
    __syncthreads();
    for (int off = 1; off < 512; off <<= 1) {
        int t = (tid >= off) ? sp[tid - off] : 0;
        __syncthreads();
        sp[tid] += t;
        __syncthreads();
    }
    if (tid < SCAN_BLOCKS) g_bsum[tid] = sp[tid] - v;   // exclusive offset
    if (tid == SCAN_BLOCKS - 1) g_row[N_NODES] = sp[tid];   // total
}

// ---------------- scan phase C: intra-block exclusive scan + offset ----------------
__global__ void block_scan_kernel() {
    int i = blockIdx.x * 256 + threadIdx.x;
    int lane = threadIdx.x & 31, warp = threadIdx.x >> 5;
    int v = (i < N_NODES) ? g_degi[i] : 0;
    int s = v;
#pragma unroll
    for (int o = 1; o < 32; o <<= 1) {
        int t = __shfl_up_sync(0xffffffffu, s, o);
        if (lane >= o) s += t;
    }
    __shared__ int ws[8];
    if (lane == 31) ws[warp] = s;
    __syncthreads();
    if (threadIdx.x == 0) {
        int run = 0;
#pragma unroll
        for (int w = 0; w < 8; w++) { int t = ws[w]; ws[w] = run; run += t; }
    }
    __syncthreads();
    int excl = (s - v) + ws[warp] + g_bsum[blockIdx.x];
    if (i < N_NODES) { g_row[i] = excl; g_cursor[i] = excl; }
}

// ---------------- scatter edges into CSR ----------------
__global__ void scatter_kernel(int E) {
    int e = blockIdx.x * blockDim.x + threadIdx.x;
    if (e >= E) return;
    int dst = g_dstbuf[e];
    int pos = atomicAdd(&g_cursor[dst], 1);
    if (pos < MAXE) g_csr[pos] = g_srcbuf[e];
}

// ---------------- agg layer 1: mean of x over in-neighbors (CSR) ----------------
__global__ void agg1_csr(const float* __restrict__ x) {
    int w    = (blockIdx.x * blockDim.x + threadIdx.x) >> 5;
    int lane = threadIdx.x & 31;
    if (w >= N_NODES) return;
    const int beg = g_row[w], end = g_row[w + 1];
    float4 a0 = {0.f, 0.f, 0.f, 0.f}, a1 = {0.f, 0.f, 0.f, 0.f};
    int i = beg;
    for (; i + 1 < end; i += 2) {
        int s0 = g_csr[i], s1 = g_csr[i + 1];
        float4 v0 = *reinterpret_cast<const float4*>(x + (size_t)s0 * CIN + lane * 4);
        float4 v1 = *reinterpret_cast<const float4*>(x + (size_t)s1 * CIN + lane * 4);
        a0.x += v0.x; a0.y += v0.y; a0.z += v0.z; a0.w += v0.w;
        a1.x += v1.x; a1.y += v1.y; a1.z += v1.z; a1.w += v1.w;
    }
    if (i < end) {
        int s0 = g_csr[i];
        float4 v0 = *reinterpret_cast<const float4*>(x + (size_t)s0 * CIN + lane * 4);
        a0.x += v0.x; a0.y += v0.y; a0.z += v0.z; a0.w += v0.w;
    }
    float rd = 1.0f / fmaxf((float)(end - beg), 1.0f);
    float4 o = {(a0.x + a1.x) * rd, (a0.y + a1.y) * rd,
                (a0.z + a1.z) * rd, (a0.w + a1.w) * rd};
    *reinterpret_cast<float4*>(g_mean1 + (size_t)w * CIN + lane * 4) = o;
}

// ---------------- agg layer 2 + final: out = mean(t) + r ----------------
__global__ void agg2_final(float* __restrict__ out) {
    int w    = (blockIdx.x * blockDim.x + threadIdx.x) >> 5;
    int lane = threadIdx.x & 31;
    if (w >= N_NODES) return;
    const int beg = g_row[w], end = g_row[w + 1];
    float2 a0 = {0.f, 0.f}, a1 = {0.f, 0.f};
    int i = beg;
    for (; i + 1 < end; i += 2) {
        int s0 = g_csr[i], s1 = g_csr[i + 1];
        float2 v0 = *reinterpret_cast<const float2*>(g_t + (size_t)s0 * COUT + lane * 2);
        float2 v1 = *reinterpret_cast<const float2*>(g_t + (size_t)s1 * COUT + lane * 2);
        a0.x += v0.x; a0.y += v0.y;
        a1.x += v1.x; a1.y += v1.y;
    }
    if (i < end) {
        int s0 = g_csr[i];
        float2 v0 = *reinterpret_cast<const float2*>(g_t + (size_t)s0 * COUT + lane * 2);
        a0.x += v0.x; a0.y += v0.y;
    }
    float rd = 1.0f / fmaxf((float)(end - beg), 1.0f);
    float2 r = *reinterpret_cast<const float2*>(g_r + (size_t)w * COUT + lane * 2);
    float2 o = {(a0.x + a1.x) * rd + r.x, (a0.y + a1.y) * rd + r.y};
    *reinterpret_cast<float2*>(out + (size_t)w * COUT + lane * 2) = o;
}

// ================= GEMMs: round-4 shape (known-good) =================
#define APITCH 66

// ---------------- GEMM layer 1 ----------------
__global__ void __launch_bounds__(256) gemm1(const float* __restrict__ x,
                                             const float* __restrict__ W1l,
                                             const float* __restrict__ W1r,
                                             const float* __restrict__ b1) {
    __shared__ __align__(16) float Ws[32 * 128];
    __shared__ __align__(16) float As[32 * APITCH];

    const int tid = threadIdx.x;
    const int block_m = blockIdx.x * 64;

    const int lm   = tid >> 2;
    const int lk0  = (tid & 3) * 8;
    const int node = block_m + lm;
    const bool valid = (node < N_NODES);

    const int c0 = (tid & 31) * 4;
    const int r0 = (tid >> 5) * 8;

    unsigned long long acc[4][4];
#pragma unroll
    for (int c = 0; c < 4; c++)
#pragma unroll
        for (int p = 0; p < 4; p++) acc[c][p] = 0ull;

    for (int ch = 0; ch < 8; ch++) {
        const int kbase = ch * 32;

#pragma unroll
        for (int i = 0; i < 16; i++) {
            int idx = tid + i * 256;
            int kk = idx >> 7, j = idx & 127;
            int k = kbase + kk;
            Ws[idx] = (k < 128) ? W1l[k * 128 + j] : W1r[(k - 128) * 128 + j];
        }

        float av[8];
        if (valid) {
            const float* p = (kbase < 128)
                ? (g_mean1 + (size_t)node * CIN + kbase + lk0)
                : (x + (size_t)node * CIN + (kbase - 128) + lk0);
#pragma unroll
            for (int j = 0; j < 8; j++) av[j] = p[j];
        } else {
#pragma unroll
            for (int j = 0; j < 8; j++) av[j] = 0.f;
        }
        __syncthreads();
#pragma unroll
        for (int j = 0; j < 8; j++) As[(lk0 + j) * APITCH + lm] = av[j];
        __syncthreads();

#pragma unroll
        for (int kk = 0; kk < 32; kk++) {
            float4 w = *reinterpret_cast<const float4*>(&Ws[kk * 128 + c0]);
            unsigned long long wd[4];
            wd[0] = dupf2(w.x); wd[1] = dupf2(w.y);
            wd[2] = dupf2(w.z); wd[3] = dupf2(w.w);
            const unsigned long long* ap =
                reinterpret_cast<const unsigned long long*>(&As[kk * APITCH + r0]);
            unsigned long long a01 = ap[0], a23 = ap[1], a45 = ap[2], a67 = ap[3];
#pragma unroll
            for (int c = 0; c < 4; c++) {
                fma2(acc[c][0], wd[c], a01);
                fma2(acc[c][1], wd[c], a23);
                fma2(acc[c][2], wd[c], a45);
                fma2(acc[c][3], wd[c], a67);
            }
        }
        __syncthreads();
    }

    float bv[4] = {b1[c0], b1[c0 + 1], b1[c0 + 2], b1[c0 + 3]};
    float res[8][4];
#pragma unroll
    for (int c = 0; c < 4; c++)
#pragma unroll
        for (int p = 0; p < 4; p++)
            unpack2(acc[c][p], res[2 * p][c], res[2 * p + 1][c]);
#pragma unroll
    for (int r = 0; r < 8; r++) {
        int n = block_m + r0 + r;
        if (n < N_NODES) {
            float4 o;
            o.x = fmaxf(res[r][0] + bv[0], 0.f);
            o.y = fmaxf(res[r][1] + bv[1], 0.f);
            o.z = fmaxf(res[r][2] + bv[2], 0.f);
            o.w = fmaxf(res[r][3] + bv[3], 0.f);
            *reinterpret_cast<float4*>(g_h + (size_t)n * CHID + c0) = o;
        }
    }
}

// ---------------- GEMM layer 2 ----------------
__global__ void __launch_bounds__(256) gemm2(const float* __restrict__ W2l,
                                             const float* __restrict__ W2r,
                                             const float* __restrict__ b2) {
    __shared__ __align__(16) float Ws[32 * 128];
    __shared__ __align__(16) float As[32 * APITCH];

    const int tid = threadIdx.x;
    const int block_m = blockIdx.x * 64;

    const int lm   = tid >> 2;
    const int lk0  = (tid & 3) * 8;
    const int node = block_m + lm;
    const bool valid = (node < N_NODES);

    const int c0 = (tid & 31) * 4;
    const int r0 = (tid >> 5) * 8;

    unsigned long long acc[4][4];
#pragma unroll
    for (int c = 0; c < 4; c++)
#pragma unroll
        for (int p = 0; p < 4; p++) acc[c][p] = 0ull;

    for (int ch = 0; ch < 4; ch++) {
        const int kbase = ch * 32;

#pragma unroll
        for (int i = 0; i < 16; i++) {
            int idx = tid + i * 256;
            int kk = idx >> 7, j = idx & 127;
            int k = kbase + kk;
            Ws[idx] = (j < 64) ? W2l[k * 64 + j] : W2r[k * 64 + (j - 64)];
        }

        float av[8];
        if (valid) {
            const float* p = g_h + (size_t)node * CHID + kbase + lk0;
#pragma unroll
            for (int j = 0; j < 8; j++) av[j] = p[j];
        } else {
#pragma unroll
            for (int j = 0; j < 8; j++) av[j] = 0.f;
        }
        __syncthreads();
#pragma unroll
        for (int j = 0; j < 8; j++) As[(lk0 + j) * APITCH + lm] = av[j];
        __syncthreads();

#pragma unroll
        for (int kk = 0; kk < 32; kk++) {
            float4 w = *reinterpret_cast<const float4*>(&Ws[kk * 128 + c0]);
            unsigned long long wd[4];
            wd[0] = dupf2(w.x); wd[1] = dupf2(w.y);
            wd[2] = dupf2(w.z); wd[3] = dupf2(w.w);
            const unsigned long long* ap =
                reinterpret_cast<const unsigned long long*>(&As[kk * APITCH + r0]);
            unsigned long long a01 = ap[0], a23 = ap[1], a45 = ap[2], a67 = ap[3];
#pragma unroll
            for (int c = 0; c < 4; c++) {
                fma2(acc[c][0], wd[c], a01);
                fma2(acc[c][1], wd[c], a23);
                fma2(acc[c][2], wd[c], a45);
                fma2(acc[c][3], wd[c], a67);
            }
        }
        __syncthreads();
    }

    float res[8][4];
#pragma unroll
    for (int c = 0; c < 4; c++)
#pragma unroll
        for (int p = 0; p < 4; p++)
            unpack2(acc[c][p], res[2 * p][c], res[2 * p + 1][c]);

    if (c0 < 64) {
#pragma unroll
        for (int r = 0; r < 8; r++) {
            int n = block_m + r0 + r;
            if (n < N_NODES) {
                float4 o = {res[r][0], res[r][1], res[r][2], res[r][3]};
                *reinterpret_cast<float4*>(g_t + (size_t)n * COUT + c0) = o;
            }
        }
    } else {
        int cc = c0 - 64;
        float bv[4] = {b2[cc], b2[cc + 1], b2[cc + 2], b2[cc + 3]};
#pragma unroll
        for (int r = 0; r < 8; r++) {
            int n = block_m + r0 + r;
            if (n < N_NODES) {
                float4 o = {res[r][0] + bv[0], res[r][1] + bv[1],
                            res[r][2] + bv[2], res[r][3] + bv[3]};
                *reinterpret_cast<float4*>(g_r + (size_t)n * COUT + cc) = o;
            }
        }
    }
}

// ---------------- launch ----------------
extern "C" void kernel_launch(void* const* d_in, const int* in_sizes, int n_in,
                              void* d_out, int out_size) {
    const float* x   = (const float*)d_in[0];
    const void*  ei  = d_in[1];
    const float* W1l = (const float*)d_in[2];
    const float* W1r = (const float*)d_in[3];
    const float* b1  = (const float*)d_in[4];
    const float* W2l = (const float*)d_in[5];
    const float* W2r = (const float*)d_in[6];
    const float* b2  = (const float*)d_in[7];
    float* out = (float*)d_out;

    const int E = in_sizes[1] / 2;

    {
        int blocks = (N_NODES + 255) / 256;
        zero_deg<<<blocks, 256>>>();
    }
    {
        long long n64_safe = (long long)E / 2;
        detect_kernel<<<1024, 256>>>((const long long*)ei, n64_safe);
    }
    {
        int blocks = (E + 255) / 256;
        decode_count<<<blocks, 256>>>(ei, E);
        block_sum_kernel<<<SCAN_BLOCKS, 256>>>();
        scan_bsum_kernel<<<1, 512>>>();
        block_scan_kernel<<<SCAN_BLOCKS, 256>>>();
        scatter_kernel<<<blocks, 256>>>(E);
    }
    {
        long long threads = (long long)N_NODES * 32;
        int blocks = (int)((threads + 255) / 256);
        agg1_csr<<<blocks, 256>>>(x);
    }
    {
        int blocks = (N_NODES + 63) / 64;
        gemm1<<<blocks, 256>>>(x, W1l, W1r, b1);
        gemm2<<<blocks, 256>>>(W2l, W2r, b2);
    }
    {
        long long threads = (long long)N_NODES * 32;
        int blocks = (int)((threads + 255) / 256);
        agg2_final<<<blocks, 256>>>(out);
    }
}

// round 10
// speedup vs baseline: 1.9915x; 1.1410x over previous
#include <cuda_runtime.h>
#include <cuda_bf16.h>
#include <cstdint>

#define N_NODES 100000
#define CIN 128
#define CHID 128
#define COUT 64
#define MAXE 1600000
#define SCAN_BLOCKS ((N_NODES + 255) / 256)

// ---------------- scratch ----------------
__device__ __align__(16) float g_mean1[(size_t)N_NODES * CIN];
__device__ __align__(16) float g_h    [(size_t)N_NODES * CHID];
__device__ __align__(16) float g_t    [(size_t)N_NODES * COUT];
__device__ __align__(16) float g_r    [(size_t)N_NODES * COUT];
__device__ int g_degi  [N_NODES];
__device__ int g_row   [N_NODES + 1];
__device__ int g_cursor[N_NODES];
__device__ int g_srcbuf[MAXE];
__device__ int g_dstbuf[MAXE];
__device__ int g_csr   [MAXE];
__device__ int g_bsum  [512];
__device__ int g_is64;

// ---------------- packed f32x2 helpers (SIMT gemm2) ----------------
__device__ __forceinline__ unsigned long long dupf2(float v) {
    unsigned long long r;
    asm("mov.b64 %0, {%1, %1};" : "=l"(r) : "r"(__float_as_uint(v)));
    return r;
}
__device__ __forceinline__ void fma2(unsigned long long& d,
                                     unsigned long long a, unsigned long long b) {
    asm("fma.rn.f32x2 %0, %1, %2, %0;" : "+l"(d) : "l"(a), "l"(b));
}
__device__ __forceinline__ void unpack2(unsigned long long p, float& lo, float& hi) {
    unsigned int l, h;
    asm("mov.b64 {%0, %1}, %2;" : "=r"(l), "=r"(h) : "l"(p));
    lo = __uint_as_float(l); hi = __uint_as_float(h);
}

// ---------------- bf16 split helpers ----------------
__device__ __forceinline__ void bf16_split2(float f0, float f1,
                                            uint32_t& hi, uint32_t& lo) {
    __nv_bfloat16 h0 = __float2bfloat16(f0);
    __nv_bfloat16 h1 = __float2bfloat16(f1);
    float r0 = f0 - __bfloat162float(h0);
    float r1 = f1 - __bfloat162float(h1);
    __nv_bfloat16 l0 = __float2bfloat16(r0);
    __nv_bfloat16 l1 = __float2bfloat16(r1);
    hi = ((uint32_t)__bfloat16_as_ushort(h1) << 16) | __bfloat16_as_ushort(h0);
    lo = ((uint32_t)__bfloat16_as_ushort(l1) << 16) | __bfloat16_as_ushort(l0);
}

// mma.sync m16n8k16 row.col f32.bf16.bf16.f32, D += A*B
__device__ __forceinline__ void mma_bf16(float* d, const uint32_t* a,
                                         const uint32_t* b) {
    asm volatile(
        "mma.sync.aligned.m16n8k16.row.col.f32.bf16.bf16.f32 "
        "{%0,%1,%2,%3}, {%4,%5,%6,%7}, {%8,%9}, {%0,%1,%2,%3};"
        : "+f"(d[0]), "+f"(d[1]), "+f"(d[2]), "+f"(d[3])
        : "r"(a[0]), "r"(a[1]), "r"(a[2]), "r"(a[3]), "r"(b[0]), "r"(b[1]));
}

// ---------------- zero deg + init flag ----------------
__global__ void zero_deg() {
    int i = blockIdx.x * blockDim.x + threadIdx.x;
    if (i < N_NODES) g_degi[i] = 0;
    if (i == 0) g_is64 = 1;
}

// ---------------- detect edge_index dtype ----------------
__global__ void detect_kernel(const long long* __restrict__ ei, long long n) {
    long long i = (long long)blockIdx.x * blockDim.x + threadIdx.x;
    long long stride = (long long)gridDim.x * blockDim.x;
    for (; i < n; i += stride) {
        unsigned long long v = (unsigned long long)ei[i];
        if (v >= (unsigned long long)N_NODES) { g_is64 = 0; return; }
    }
}

// ---------------- decode edges + degree histogram ----------------
__global__ void decode_count(const void* __restrict__ ei_raw, int E) {
    int e = blockIdx.x * blockDim.x + threadIdx.x;
    if (e >= E) return;
    int src, dst;
    if (g_is64) {
        const long long* ei = (const long long*)ei_raw;
        src = (int)ei[e]; dst = (int)ei[(size_t)E + e];
    } else {
        const int* ei = (const int*)ei_raw;
        src = ei[e]; dst = ei[(size_t)E + e];
    }
    if ((unsigned)src >= N_NODES) src = 0;
    if ((unsigned)dst >= N_NODES) dst = 0;
    g_srcbuf[e] = src;
    g_dstbuf[e] = dst;
    atomicAdd(&g_degi[dst], 1);
}

// ---------------- scan phases ----------------
__global__ void block_sum_kernel() {
    int i = blockIdx.x * 256 + threadIdx.x;
    int v = (i < N_NODES) ? g_degi[i] : 0;
#pragma unroll
    for (int o = 16; o; o >>= 1) v += __shfl_down_sync(0xffffffffu, v, o);
    __shared__ int ws[8];
    if ((threadIdx.x & 31) == 0) ws[threadIdx.x >> 5] = v;
    __syncthreads();
    if (threadIdx.x < 8) {
        int s = ws[threadIdx.x];
#pragma unroll
        for (int o = 4; o; o >>= 1) s += __shfl_down_sync(0xffu, s, o);
        if (threadIdx.x == 0) g_bsum[blockIdx.x] = s;
    }
}

__global__ void scan_bsum_kernel() {
    __shared__ int sp[512];
    int tid = threadIdx.x;
    int v = (tid < SCAN_BLOCKS) ? g_bsum[tid] : 0;
    sp[tid] = v;
    __syncthreads();
    for (int off = 1; off < 512; off <<= 1) {
        int t = (tid >= off) ? sp[tid - off] : 0;
        __syncthreads();
        sp[tid] += t;
        __syncthreads();
    }
    if (tid < SCAN_BLOCKS) g_bsum[tid] = sp[tid] - v;
    if (tid == SCAN_BLOCKS - 1) g_row[N_NODES] = sp[tid];
}

__global__ void block_scan_kernel() {
    int i = blockIdx.x * 256 + threadIdx.x;
    int lane = threadIdx.x & 31, warp = threadIdx.x >> 5;
    int v = (i < N_NODES) ? g_degi[i] : 0;
    int s = v;
#pragma unroll
    for (int o = 1; o < 32; o <<= 1) {
        int t = __shfl_up_sync(0xffffffffu, s, o);
        if (lane >= o) s += t;
    }
    __shared__ int ws[8];
    if (lane == 31) ws[warp] = s;
    __syncthreads();
    if (threadIdx.x == 0) {
        int run = 0;
#pragma unroll
        for (int w = 0; w < 8; w++) { int t = ws[w]; ws[w] = run; run += t; }
    }
    __syncthreads();
    int excl = (s - v) + ws[warp] + g_bsum[blockIdx.x];
    if (i < N_NODES) { g_row[i] = excl; g_cursor[i] = excl; }
}

__global__ void scatter_kernel(int E) {
    int e = blockIdx.x * blockDim.x + threadIdx.x;
    if (e >= E) return;
    int dst = g_dstbuf[e];
    int pos = atomicAdd(&g_cursor[dst], 1);
    if (pos < MAXE) g_csr[pos] = g_srcbuf[e];
}

// ---------------- agg layer 1 ----------------
__global__ void agg1_csr(const float* __restrict__ x) {
    int w    = (blockIdx.x * blockDim.x + threadIdx.x) >> 5;
    int lane = threadIdx.x & 31;
    if (w >= N_NODES) return;
    const int beg = g_row[w], end = g_row[w + 1];
    float4 a0 = {0.f, 0.f, 0.f, 0.f}, a1 = {0.f, 0.f, 0.f, 0.f};
    int i = beg;
    for (; i + 1 < end; i += 2) {
        int s0 = g_csr[i], s1 = g_csr[i + 1];
        float4 v0 = *reinterpret_cast<const float4*>(x + (size_t)s0 * CIN + lane * 4);
        float4 v1 = *reinterpret_cast<const float4*>(x + (size_t)s1 * CIN + lane * 4);
        a0.x += v0.x; a0.y += v0.y; a0.z += v0.z; a0.w += v0.w;
        a1.x += v1.x; a1.y += v1.y; a1.z += v1.z; a1.w += v1.w;
    }
    if (i < end) {
        int s0 = g_csr[i];
        float4 v0 = *reinterpret_cast<const float4*>(x + (size_t)s0 * CIN + lane * 4);
        a0.x += v0.x; a0.y += v0.y; a0.z += v0.z; a0.w += v0.w;
    }
    float rd = 1.0f / fmaxf((float)(end - beg), 1.0f);
    float4 o = {(a0.x + a1.x) * rd, (a0.y + a1.y) * rd,
                (a0.z + a1.z) * rd, (a0.w + a1.w) * rd};
    *reinterpret_cast<float4*>(g_mean1 + (size_t)w * CIN + lane * 4) = o;
}

// ---------------- agg layer 2 + final ----------------
__global__ void agg2_final(float* __restrict__ out) {
    int w    = (blockIdx.x * blockDim.x + threadIdx.x) >> 5;
    int lane = threadIdx.x & 31;
    if (w >= N_NODES) return;
    const int beg = g_row[w], end = g_row[w + 1];
    float2 a0 = {0.f, 0.f}, a1 = {0.f, 0.f};
    int i = beg;
    for (; i + 1 < end; i += 2) {
        int s0 = g_csr[i], s1 = g_csr[i + 1];
        float2 v0 = *reinterpret_cast<const float2*>(g_t + (size_t)s0 * COUT + lane * 2);
        float2 v1 = *reinterpret_cast<const float2*>(g_t + (size_t)s1 * COUT + lane * 2);
        a0.x += v0.x; a0.y += v0.y;
        a1.x += v1.x; a1.y += v1.y;
    }
    if (i < end) {
        int s0 = g_csr[i];
        float2 v0 = *reinterpret_cast<const float2*>(g_t + (size_t)s0 * COUT + lane * 2);
        a0.x += v0.x; a0.y += v0.y;
    }
    float rd = 1.0f / fmaxf((float)(end - beg), 1.0f);
    float2 r = *reinterpret_cast<const float2*>(g_r + (size_t)w * COUT + lane * 2);
    float2 o = {(a0.x + a1.x) * rd + r.x, (a0.y + a1.y) * rd + r.y};
    *reinterpret_cast<float2*>(out + (size_t)w * COUT + lane * 2) = o;
}

// ================= GEMM layer 1: mma.sync bf16-split =================
// h = relu([mean1 | x] @ [W1l ; W1r] + b1)   A:[N,256]  W:[256,128]
// BM=64, BN=128, BK=32; 8 warps, warp tile 16x64 (8 n-frags of m16n8k16).
// A smem [64 rows][32 k] bf16 pitch-40; W smem TRANSPOSED [128 n][32 k] pitch-40.
// D = Ahi*Bhi + Ahi*Blo + Alo*Bhi  (fp32 regs).
__global__ void __launch_bounds__(256) gemm1_mma(const float* __restrict__ x,
                                                 const float* __restrict__ W1l,
                                                 const float* __restrict__ W1r,
                                                 const float* __restrict__ b1) {
    // pitch 20 u32 = 40 bf16 per row
    __shared__ uint32_t sAhi[64 * 20], sAlo[64 * 20];
    __shared__ uint32_t sBhi[128 * 20], sBlo[128 * 20];

    const int tid  = threadIdx.x;
    const int lane = tid & 31;
    const int wid  = tid >> 5;
    const int g    = lane >> 2;      // group 0..7
    const int tig  = lane & 3;       // thread-in-group
    const int r0w  = (wid & 3) * 16; // warp row base
    const int n0w  = (wid >> 2) * 64;// warp col base
    const int block_m = blockIdx.x * 64;

    // A loader: row = tid>>2 (0..63), 8 k at akq
    const int arow = tid >> 2;
    const int akq  = (tid & 3) * 8;
    const int anode = block_m + arow;
    const bool avalid = (anode < N_NODES);
    // W loader: n = tid&127, k-half = tid>>7
    const int wn  = tid & 127;
    const int wkh = tid >> 7;

    float acc[8][4];
#pragma unroll
    for (int nf = 0; nf < 8; nf++)
#pragma unroll
        for (int q = 0; q < 4; q++) acc[nf][q] = 0.f;

    for (int ch = 0; ch < 8; ch++) {
        const int kbase = ch * 32;

        // ---- A chunk: fp32 -> bf16 hi/lo ----
        {
            float v[8];
            if (avalid) {
                const float* src = (kbase < 128)
                    ? (g_mean1 + (size_t)anode * CIN + kbase + akq)
                    : (x + (size_t)anode * CIN + (kbase - 128) + akq);
                const float4* p = reinterpret_cast<const float4*>(src);
                float4 t0 = p[0], t1 = p[1];
                v[0]=t0.x; v[1]=t0.y; v[2]=t0.z; v[3]=t0.w;
                v[4]=t1.x; v[5]=t1.y; v[6]=t1.z; v[7]=t1.w;
            } else {
#pragma unroll
                for (int j = 0; j < 8; j++) v[j] = 0.f;
            }
            const int base = arow * 20 + (akq >> 1);
#pragma unroll
            for (int j = 0; j < 4; j++) {
                uint32_t hi, lo;
                bf16_split2(v[2*j], v[2*j+1], hi, lo);
                sAhi[base + j] = hi;
                sAlo[base + j] = lo;
            }
        }
        // ---- W chunk: fp32 -> bf16 hi/lo, transposed [n][k] ----
        {
#pragma unroll
            for (int i = 0; i < 8; i++) {
                const int k  = wkh * 16 + 2 * i;
                const int k0 = kbase + k;
                const float* w0 = (k0 < 128) ? (W1l + (size_t)k0 * 128)
                                             : (W1r + (size_t)(k0 - 128) * 128);
                const float* w1 = (k0 + 1 < 128) ? (W1l + (size_t)(k0 + 1) * 128)
                                                 : (W1r + (size_t)(k0 + 1 - 128) * 128);
                uint32_t hi, lo;
                bf16_split2(w0[wn], w1[wn], hi, lo);
                sBhi[wn * 20 + (k >> 1)] = hi;
                sBlo[wn * 20 + (k >> 1)] = lo;
            }
        }
        __syncthreads();

        // ---- 2 k16 steps ----
#pragma unroll
        for (int ks = 0; ks < 2; ks++) {
            const int kof = ks * 8;   // u32 offset of k16 within pitch-20 row
            uint32_t ah[4], al[4];
            {
                const int i0 = (r0w + g) * 20 + kof + tig;
                const int i1 = (r0w + g + 8) * 20 + kof + tig;
                ah[0] = sAhi[i0];     ah[1] = sAhi[i1];
                ah[2] = sAhi[i0 + 4]; ah[3] = sAhi[i1 + 4];
                al[0] = sAlo[i0];     al[1] = sAlo[i1];
                al[2] = sAlo[i0 + 4]; al[3] = sAlo[i1 + 4];
            }
#pragma unroll
            for (int nf = 0; nf < 8; nf++) {
                const int nb = (n0w + nf * 8 + g) * 20 + kof + tig;
                uint32_t bh[2] = { sBhi[nb], sBhi[nb + 4] };
                uint32_t bl[2] = { sBlo[nb], sBlo[nb + 4] };
                mma_bf16(acc[nf], ah, bh);
                mma_bf16(acc[nf], ah, bl);
                mma_bf16(acc[nf], al, bh);
            }
        }
        __syncthreads();
    }

    // ---- epilogue: bias + relu -> g_h ----
    const int row0 = block_m + r0w + g;
    const int row1 = row0 + 8;
#pragma unroll
    for (int nf = 0; nf < 8; nf++) {
        const int col = n0w + nf * 8 + 2 * tig;
        const float bb0 = b1[col], bb1 = b1[col + 1];
        if (row0 < N_NODES) {
            float2 o = {fmaxf(acc[nf][0] + bb0, 0.f), fmaxf(acc[nf][1] + bb1, 0.f)};
            *reinterpret_cast<float2*>(g_h + (size_t)row0 * CHID + col) = o;
        }
        if (row1 < N_NODES) {
            float2 o = {fmaxf(acc[nf][2] + bb0, 0.f), fmaxf(acc[nf][3] + bb1, 0.f)};
            *reinterpret_cast<float2*>(g_h + (size_t)row1 * CHID + col) = o;
        }
    }
}

// ================= GEMM layer 2: SIMT FFMA2 (known-good round-4 shape) =================
#define APITCH 66

__global__ void __launch_bounds__(256) gemm2(const float* __restrict__ W2l,
                                             const float* __restrict__ W2r,
                                             const float* __restrict__ b2) {
    __shared__ __align__(16) float Ws[32 * 128];
    __shared__ __align__(16) float As[32 * APITCH];

    const int tid = threadIdx.x;
    const int block_m = blockIdx.x * 64;

    const int lm   = tid >> 2;
    const int lk0  = (tid & 3) * 8;
    const int node = block_m + lm;
    const bool valid = (node < N_NODES);

    const int c0 = (tid & 31) * 4;
    const int r0 = (tid >> 5) * 8;

    unsigned long long acc[4][4];
#pragma unroll
    for (int c = 0; c < 4; c++)
#pragma unroll
        for (int p = 0; p < 4; p++) acc[c][p] = 0ull;

    for (int ch = 0; ch < 4; ch++) {
        const int kbase = ch * 32;

#pragma unroll
        for (int i = 0; i < 16; i++) {
            int idx = tid + i * 256;
            int kk = idx >> 7, j = idx & 127;
            int k = kbase + kk;
            Ws[idx] = (j < 64) ? W2l[k * 64 + j] : W2r[k * 64 + (j - 64)];
        }

        float av[8];
        if (valid) {
            const float* p = g_h + (size_t)node * CHID + kbase + lk0;
#pragma unroll
            for (int j = 0; j < 8; j++) av[j] = p[j];
        } else {
#pragma unroll
            for (int j = 0; j < 8; j++) av[j] = 0.f;
        }
        __syncthreads();
#pragma unroll
        for (int j = 0; j < 8; j++) As[(lk0 + j) * APITCH + lm] = av[j];
        __syncthreads();

#pragma unroll
        for (int kk = 0; kk < 32; kk++) {
            float4 w = *reinterpret_cast<const float4*>(&Ws[kk * 128 + c0]);
            unsigned long long wd[4];
            wd[0] = dupf2(w.x); wd[1] = dupf2(w.y);
            wd[2] = dupf2(w.z); wd[3] = dupf2(w.w);
            const unsigned long long* ap =
                reinterpret_cast<const unsigned long long*>(&As[kk * APITCH + r0]);
            unsigned long long a01 = ap[0], a23 = ap[1], a45 = ap[2], a67 = ap[3];
#pragma unroll
            for (int c = 0; c < 4; c++) {
                fma2(acc[c][0], wd[c], a01);
                fma2(acc[c][1], wd[c], a23);
                fma2(acc[c][2], wd[c], a45);
                fma2(acc[c][3], wd[c], a67);
            }
        }
        __syncthreads();
    }

    float res[8][4];
#pragma unroll
    for (int c = 0; c < 4; c++)
#pragma unroll
        for (int p = 0; p < 4; p++)
            unpack2(acc[c][p], res[2 * p][c], res[2 * p + 1][c]);

    if (c0 < 64) {
#pragma unroll
        for (int r = 0; r < 8; r++) {
            int n = block_m + r0 + r;
            if (n < N_NODES) {
                float4 o = {res[r][0], res[r][1], res[r][2], res[r][3]};
                *reinterpret_cast<float4*>(g_t + (size_t)n * COUT + c0) = o;
            }
        }
    } else {
        int cc = c0 - 64;
        float bv[4] = {b2[cc], b2[cc + 1], b2[cc + 2], b2[cc + 3]};
#pragma unroll
        for (int r = 0; r < 8; r++) {
            int n = block_m + r0 + r;
            if (n < N_NODES) {
                float4 o = {res[r][0] + bv[0], res[r][1] + bv[1],
                            res[r][2] + bv[2], res[r][3] + bv[3]};
                *reinterpret_cast<float4*>(g_r + (size_t)n * COUT + cc) = o;
            }
        }
    }
}

// ---------------- launch ----------------
extern "C" void kernel_launch(void* const* d_in, const int* in_sizes, int n_in,
                              void* d_out, int out_size) {
    const float* x   = (const float*)d_in[0];
    const void*  ei  = d_in[1];
    const float* W1l = (const float*)d_in[2];
    const float* W1r = (const float*)d_in[3];
    const float* b1  = (const float*)d_in[4];
    const float* W2l = (const float*)d_in[5];
    const float* W2r = (const float*)d_in[6];
    const float* b2  = (const float*)d_in[7];
    float* out = (float*)d_out;

    const int E = in_sizes[1] / 2;

    {
        int blocks = (N_NODES + 255) / 256;
        zero_deg<<<blocks, 256>>>();
    }
    {
        long long n64_safe = (long long)E / 2;
        detect_kernel<<<1024, 256>>>((const long long*)ei, n64_safe);
    }
    {
        int blocks = (E + 255) / 256;
        decode_count<<<blocks, 256>>>(ei, E);
        block_sum_kernel<<<SCAN_BLOCKS, 256>>>();
        scan_bsum_kernel<<<1, 512>>>();
        block_scan_kernel<<<SCAN_BLOCKS, 256>>>();
        scatter_kernel<<<blocks, 256>>>(E);
    }
    {
        long long threads = (long long)N_NODES * 32;
        int blocks = (int)((threads + 255) / 256);
        agg1_csr<<<blocks, 256>>>(x);
    }
    {
        int blocks = (N_NODES + 63) / 64;
        gemm1_mma<<<blocks, 256>>>(x, W1l, W1r, b1);
        gemm2<<<blocks, 256>>>(W2l, W2r, b2);
    }
    {
        long long threads = (long long)N_NODES * 32;
        int blocks = (int)((threads + 255) / 256);
        agg2_final<<<blocks, 256>>>(out);
    }
}

// round 11
// speedup vs baseline: 2.1736x; 1.0915x over previous
#include <cuda_runtime.h>
#include <cuda_bf16.h>
#include <cstdint>

#define N_NODES 100000
#define CIN 128
#define CHID 128
#define COUT 64
#define MAXE 1600000
#define SCAN_BLOCKS ((N_NODES + 255) / 256)

// ---------------- scratch ----------------
__device__ __align__(16) float g_mean1[(size_t)N_NODES * CIN];
__device__ __align__(16) float g_h    [(size_t)N_NODES * CHID];
__device__ __align__(16) float g_t    [(size_t)N_NODES * COUT];
__device__ __align__(16) float g_r    [(size_t)N_NODES * COUT];
__device__ int g_degi  [N_NODES];
__device__ int g_row   [N_NODES + 1];
__device__ int g_cursor[N_NODES];
__device__ int g_srcbuf[MAXE];
__device__ int g_dstbuf[MAXE];
__device__ int g_csr   [MAXE];
__device__ int g_bsum  [512];
__device__ int g_is64;

// ---------------- bf16 split helpers ----------------
__device__ __forceinline__ void bf16_split2(float f0, float f1,
                                            uint32_t& hi, uint32_t& lo) {
    __nv_bfloat16 h0 = __float2bfloat16(f0);
    __nv_bfloat16 h1 = __float2bfloat16(f1);
    float r0 = f0 - __bfloat162float(h0);
    float r1 = f1 - __bfloat162float(h1);
    __nv_bfloat16 l0 = __float2bfloat16(r0);
    __nv_bfloat16 l1 = __float2bfloat16(r1);
    hi = ((uint32_t)__bfloat16_as_ushort(h1) << 16) | __bfloat16_as_ushort(h0);
    lo = ((uint32_t)__bfloat16_as_ushort(l1) << 16) | __bfloat16_as_ushort(l0);
}

// mma.sync m16n8k16 row.col f32.bf16.bf16.f32, D += A*B
__device__ __forceinline__ void mma_bf16(float* d, const uint32_t* a,
                                         const uint32_t* b) {
    asm volatile(
        "mma.sync.aligned.m16n8k16.row.col.f32.bf16.bf16.f32 "
        "{%0,%1,%2,%3}, {%4,%5,%6,%7}, {%8,%9}, {%0,%1,%2,%3};"
        : "+f"(d[0]), "+f"(d[1]), "+f"(d[2]), "+f"(d[3])
        : "r"(a[0]), "r"(a[1]), "r"(a[2]), "r"(a[3]), "r"(b[0]), "r"(b[1]));
}

// ---------------- zero deg + init flag ----------------
__global__ void zero_deg() {
    int i = blockIdx.x * blockDim.x + threadIdx.x;
    if (i < N_NODES) g_degi[i] = 0;
    if (i == 0) g_is64 = 1;
}

// ---------------- detect edge_index dtype ----------------
__global__ void detect_kernel(const long long* __restrict__ ei, long long n) {
    long long i = (long long)blockIdx.x * blockDim.x + threadIdx.x;
    long long stride = (long long)gridDim.x * blockDim.x;
    for (; i < n; i += stride) {
        unsigned long long v = (unsigned long long)ei[i];
        if (v >= (unsigned long long)N_NODES) { g_is64 = 0; return; }
    }
}

// ---------------- decode edges + degree histogram ----------------
__global__ void decode_count(const void* __restrict__ ei_raw, int E) {
    int e = blockIdx.x * blockDim.x + threadIdx.x;
    if (e >= E) return;
    int src, dst;
    if (g_is64) {
        const long long* ei = (const long long*)ei_raw;
        src = (int)ei[e]; dst = (int)ei[(size_t)E + e];
    } else {
        const int* ei = (const int*)ei_raw;
        src = ei[e]; dst = ei[(size_t)E + e];
    }
    if ((unsigned)src >= N_NODES) src = 0;
    if ((unsigned)dst >= N_NODES) dst = 0;
    g_srcbuf[e] = src;
    g_dstbuf[e] = dst;
    atomicAdd(&g_degi[dst], 1);
}

// ---------------- scan phases ----------------
__global__ void block_sum_kernel() {
    int i = blockIdx.x * 256 + threadIdx.x;
    int v = (i < N_NODES) ? g_degi[i] : 0;
#pragma unroll
    for (int o = 16; o; o >>= 1) v += __shfl_down_sync(0xffffffffu, v, o);
    __shared__ int ws[8];
    if ((threadIdx.x & 31) == 0) ws[threadIdx.x >> 5] = v;
    __syncthreads();
    if (threadIdx.x < 8) {
        int s = ws[threadIdx.x];
#pragma unroll
        for (int o = 4; o; o >>= 1) s += __shfl_down_sync(0xffu, s, o);
        if (threadIdx.x == 0) g_bsum[blockIdx.x] = s;
    }
}

__global__ void scan_bsum_kernel() {
    __shared__ int sp[512];
    int tid = threadIdx.x;
    int v = (tid < SCAN_BLOCKS) ? g_bsum[tid] : 0;
    sp[tid] = v;
    __syncthreads();
    for (int off = 1; off < 512; off <<= 1) {
        int t = (tid >= off) ? sp[tid - off] : 0;
        __syncthreads();
        sp[tid] += t;
        __syncthreads();
    }
    if (tid < SCAN_BLOCKS) g_bsum[tid] = sp[tid] - v;
    if (tid == SCAN_BLOCKS - 1) g_row[N_NODES] = sp[tid];
}

__global__ void block_scan_kernel() {
    int i = blockIdx.x * 256 + threadIdx.x;
    int lane = threadIdx.x & 31, warp = threadIdx.x >> 5;
    int v = (i < N_NODES) ? g_degi[i] : 0;
    int s = v;
#pragma unroll
    for (int o = 1; o < 32; o <<= 1) {
        int t = __shfl_up_sync(0xffffffffu, s, o);
        if (lane >= o) s += t;
    }
    __shared__ int ws[8];
    if (lane == 31) ws[warp] = s;
    __syncthreads();
    if (threadIdx.x == 0) {
        int run = 0;
#pragma unroll
        for (int w = 0; w < 8; w++) { int t = ws[w]; ws[w] = run; run += t; }
    }
    __syncthreads();
    int excl = (s - v) + ws[warp] + g_bsum[blockIdx.x];
    if (i < N_NODES) { g_row[i] = excl; g_cursor[i] = excl; }
}

__global__ void scatter_kernel(int E) {
    int e = blockIdx.x * blockDim.x + threadIdx.x;
    if (e >= E) return;
    int dst = g_dstbuf[e];
    int pos = atomicAdd(&g_cursor[dst], 1);
    if (pos < MAXE) g_csr[pos] = g_srcbuf[e];
}

// ---------------- agg layer 1 ----------------
__global__ void agg1_csr(const float* __restrict__ x) {
    int w    = (blockIdx.x * blockDim.x + threadIdx.x) >> 5;
    int lane = threadIdx.x & 31;
    if (w >= N_NODES) return;
    const int beg = g_row[w], end = g_row[w + 1];
    float4 a0 = {0.f, 0.f, 0.f, 0.f}, a1 = {0.f, 0.f, 0.f, 0.f};
    int i = beg;
    for (; i + 1 < end; i += 2) {
        int s0 = g_csr[i], s1 = g_csr[i + 1];
        float4 v0 = *reinterpret_cast<const float4*>(x + (size_t)s0 * CIN + lane * 4);
        float4 v1 = *reinterpret_cast<const float4*>(x + (size_t)s1 * CIN + lane * 4);
        a0.x += v0.x; a0.y += v0.y; a0.z += v0.z; a0.w += v0.w;
        a1.x += v1.x; a1.y += v1.y; a1.z += v1.z; a1.w += v1.w;
    }
    if (i < end) {
        int s0 = g_csr[i];
        float4 v0 = *reinterpret_cast<const float4*>(x + (size_t)s0 * CIN + lane * 4);
        a0.x += v0.x; a0.y += v0.y; a0.z += v0.z; a0.w += v0.w;
    }
    float rd = 1.0f / fmaxf((float)(end - beg), 1.0f);
    float4 o = {(a0.x + a1.x) * rd, (a0.y + a1.y) * rd,
                (a0.z + a1.z) * rd, (a0.w + a1.w) * rd};
    *reinterpret_cast<float4*>(g_mean1 + (size_t)w * CIN + lane * 4) = o;
}

// ---------------- agg layer 2 + final ----------------
__global__ void agg2_final(float* __restrict__ out) {
    int w    = (blockIdx.x * blockDim.x + threadIdx.x) >> 5;
    int lane = threadIdx.x & 31;
    if (w >= N_NODES) return;
    const int beg = g_row[w], end = g_row[w + 1];
    float2 a0 = {0.f, 0.f}, a1 = {0.f, 0.f};
    int i = beg;
    for (; i + 1 < end; i += 2) {
        int s0 = g_csr[i], s1 = g_csr[i + 1];
        float2 v0 = *reinterpret_cast<const float2*>(g_t + (size_t)s0 * COUT + lane * 2);
        float2 v1 = *reinterpret_cast<const float2*>(g_t + (size_t)s1 * COUT + lane * 2);
        a0.x += v0.x; a0.y += v0.y;
        a1.x += v1.x; a1.y += v1.y;
    }
    if (i < end) {
        int s0 = g_csr[i];
        float2 v0 = *reinterpret_cast<const float2*>(g_t + (size_t)s0 * COUT + lane * 2);
        a0.x += v0.x; a0.y += v0.y;
    }
    float rd = 1.0f / fmaxf((float)(end - beg), 1.0f);
    float2 r = *reinterpret_cast<const float2*>(g_r + (size_t)w * COUT + lane * 2);
    float2 o = {(a0.x + a1.x) * rd + r.x, (a0.y + a1.y) * rd + r.y};
    *reinterpret_cast<float2*>(out + (size_t)w * COUT + lane * 2) = o;
}

// ================= GEMM layer 1: mma.sync bf16-split (verified R10) =================
// h = relu([mean1 | x] @ [W1l ; W1r] + b1)   A:[N,256]  W:[256,128]
// BM=64, BN=128, BK=32; 8 warps, warp tile 16x64 (8 n-frags of m16n8k16).
__global__ void __launch_bounds__(256) gemm1_mma(const float* __restrict__ x,
                                                 const float* __restrict__ W1l,
                                                 const float* __restrict__ W1r,
                                                 const float* __restrict__ b1) {
    __shared__ uint32_t sAhi[64 * 20], sAlo[64 * 20];
    __shared__ uint32_t sBhi[128 * 20], sBlo[128 * 20];

    const int tid  = threadIdx.x;
    const int lane = tid & 31;
    const int wid  = tid >> 5;
    const int g    = lane >> 2;
    const int tig  = lane & 3;
    const int r0w  = (wid & 3) * 16;
    const int n0w  = (wid >> 2) * 64;
    const int block_m = blockIdx.x * 64;

    const int arow = tid >> 2;
    const int akq  = (tid & 3) * 8;
    const int anode = block_m + arow;
    const bool avalid = (anode < N_NODES);
    const int wn  = tid & 127;
    const int wkh = tid >> 7;

    float acc[8][4];
#pragma unroll
    for (int nf = 0; nf < 8; nf++)
#pragma unroll
        for (int q = 0; q < 4; q++) acc[nf][q] = 0.f;

    for (int ch = 0; ch < 8; ch++) {
        const int kbase = ch * 32;

        {
            float v[8];
            if (avalid) {
                const float* src = (kbase < 128)
                    ? (g_mean1 + (size_t)anode * CIN + kbase + akq)
                    : (x + (size_t)anode * CIN + (kbase - 128) + akq);
                const float4* p = reinterpret_cast<const float4*>(src);
                float4 t0 = p[0], t1 = p[1];
                v[0]=t0.x; v[1]=t0.y; v[2]=t0.z; v[3]=t0.w;
                v[4]=t1.x; v[5]=t1.y; v[6]=t1.z; v[7]=t1.w;
            } else {
#pragma unroll
                for (int j = 0; j < 8; j++) v[j] = 0.f;
            }
            const int base = arow * 20 + (akq >> 1);
#pragma unroll
            for (int j = 0; j < 4; j++) {
                uint32_t hi, lo;
                bf16_split2(v[2*j], v[2*j+1], hi, lo);
                sAhi[base + j] = hi;
                sAlo[base + j] = lo;
            }
        }
        {
#pragma unroll
            for (int i = 0; i < 8; i++) {
                const int k  = wkh * 16 + 2 * i;
                const int k0 = kbase + k;
                const float* w0 = (k0 < 128) ? (W1l + (size_t)k0 * 128)
                                             : (W1r + (size_t)(k0 - 128) * 128);
                const float* w1 = (k0 + 1 < 128) ? (W1l + (size_t)(k0 + 1) * 128)
                                                 : (W1r + (size_t)(k0 + 1 - 128) * 128);
                uint32_t hi, lo;
                bf16_split2(w0[wn], w1[wn], hi, lo);
                sBhi[wn * 20 + (k >> 1)] = hi;
                sBlo[wn * 20 + (k >> 1)] = lo;
            }
        }
        __syncthreads();

#pragma unroll
        for (int ks = 0; ks < 2; ks++) {
            const int kof = ks * 8;
            uint32_t ah[4], al[4];
            {
                const int i0 = (r0w + g) * 20 + kof + tig;
                const int i1 = (r0w + g + 8) * 20 + kof + tig;
                ah[0] = sAhi[i0];     ah[1] = sAhi[i1];
                ah[2] = sAhi[i0 + 4]; ah[3] = sAhi[i1 + 4];
                al[0] = sAlo[i0];     al[1] = sAlo[i1];
                al[2] = sAlo[i0 + 4]; al[3] = sAlo[i1 + 4];
            }
#pragma unroll
            for (int nf = 0; nf < 8; nf++) {
                const int nb = (n0w + nf * 8 + g) * 20 + kof + tig;
                uint32_t bh[2] = { sBhi[nb], sBhi[nb + 4] };
                uint32_t bl[2] = { sBlo[nb], sBlo[nb + 4] };
                mma_bf16(acc[nf], ah, bh);
                mma_bf16(acc[nf], ah, bl);
                mma_bf16(acc[nf], al, bh);
            }
        }
        __syncthreads();
    }

    const int row0 = block_m + r0w + g;
    const int row1 = row0 + 8;
#pragma unroll
    for (int nf = 0; nf < 8; nf++) {
        const int col = n0w + nf * 8 + 2 * tig;
        const float bb0 = b1[col], bb1 = b1[col + 1];
        if (row0 < N_NODES) {
            float2 o = {fmaxf(acc[nf][0] + bb0, 0.f), fmaxf(acc[nf][1] + bb1, 0.f)};
            *reinterpret_cast<float2*>(g_h + (size_t)row0 * CHID + col) = o;
        }
        if (row1 < N_NODES) {
            float2 o = {fmaxf(acc[nf][2] + bb0, 0.f), fmaxf(acc[nf][3] + bb1, 0.f)};
            *reinterpret_cast<float2*>(g_h + (size_t)row1 * CHID + col) = o;
        }
    }
}

// ================= GEMM layer 2: mma.sync bf16-split (same skeleton, K=128) =================
// [t | r] = h @ [W2l | W2r] (+ [0 | b2])   A:[N,128]  W:[128,128]
__global__ void __launch_bounds__(256) gemm2_mma(const float* __restrict__ W2l,
                                                 const float* __restrict__ W2r,
                                                 const float* __restrict__ b2) {
    __shared__ uint32_t sAhi[64 * 20], sAlo[64 * 20];
    __shared__ uint32_t sBhi[128 * 20], sBlo[128 * 20];

    const int tid  = threadIdx.x;
    const int lane = tid & 31;
    const int wid  = tid >> 5;
    const int g    = lane >> 2;
    const int tig  = lane & 3;
    const int r0w  = (wid & 3) * 16;
    const int n0w  = (wid >> 2) * 64;
    const int block_m = blockIdx.x * 64;

    const int arow = tid >> 2;
    const int akq  = (tid & 3) * 8;
    const int anode = block_m + arow;
    const bool avalid = (anode < N_NODES);
    const int wn  = tid & 127;   // output col 0..127 ([W2l | W2r])
    const int wkh = tid >> 7;

    float acc[8][4];
#pragma unroll
    for (int nf = 0; nf < 8; nf++)
#pragma unroll
        for (int q = 0; q < 4; q++) acc[nf][q] = 0.f;

    for (int ch = 0; ch < 4; ch++) {
        const int kbase = ch * 32;

        // ---- A chunk from g_h ----
        {
            float v[8];
            if (avalid) {
                const float4* p = reinterpret_cast<const float4*>(
                    g_h + (size_t)anode * CHID + kbase + akq);
                float4 t0 = p[0], t1 = p[1];
                v[0]=t0.x; v[1]=t0.y; v[2]=t0.z; v[3]=t0.w;
                v[4]=t1.x; v[5]=t1.y; v[6]=t1.z; v[7]=t1.w;
            } else {
#pragma unroll
                for (int j = 0; j < 8; j++) v[j] = 0.f;
            }
            const int base = arow * 20 + (akq >> 1);
#pragma unroll
            for (int j = 0; j < 4; j++) {
                uint32_t hi, lo;
                bf16_split2(v[2*j], v[2*j+1], hi, lo);
                sAhi[base + j] = hi;
                sAlo[base + j] = lo;
            }
        }
        // ---- W chunk: [W2l | W2r] col-concat, transposed [n][k] ----
        {
            const float* wbase = (wn < 64) ? (W2l + wn) : (W2r + (wn - 64));
#pragma unroll
            for (int i = 0; i < 8; i++) {
                const int k  = wkh * 16 + 2 * i;
                const int k0 = kbase + k;
                float a = wbase[(size_t)k0 * 64];
                float c = wbase[(size_t)(k0 + 1) * 64];
                uint32_t hi, lo;
                bf16_split2(a, c, hi, lo);
                sBhi[wn * 20 + (k >> 1)] = hi;
                sBlo[wn * 20 + (k >> 1)] = lo;
            }
        }
        __syncthreads();

#pragma unroll
        for (int ks = 0; ks < 2; ks++) {
            const int kof = ks * 8;
            uint32_t ah[4], al[4];
            {
                const int i0 = (r0w + g) * 20 + kof + tig;
                const int i1 = (r0w + g + 8) * 20 + kof + tig;
                ah[0] = sAhi[i0];     ah[1] = sAhi[i1];
                ah[2] = sAhi[i0 + 4]; ah[3] = sAhi[i1 + 4];
                al[0] = sAlo[i0];     al[1] = sAlo[i1];
                al[2] = sAlo[i0 + 4]; al[3] = sAlo[i1 + 4];
            }
#pragma unroll
            for (int nf = 0; nf < 8; nf++) {
                const int nb = (n0w + nf * 8 + g) * 20 + kof + tig;
                uint32_t bh[2] = { sBhi[nb], sBhi[nb + 4] };
                uint32_t bl[2] = { sBlo[nb], sBlo[nb + 4] };
                mma_bf16(acc[nf], ah, bh);
                mma_bf16(acc[nf], ah, bl);
                mma_bf16(acc[nf], al, bh);
            }
        }
        __syncthreads();
    }

    // ---- epilogue: cols [0,64) -> g_t (no bias); cols [64,128) -> g_r + b2 ----
    const int row0 = block_m + r0w + g;
    const int row1 = row0 + 8;
#pragma unroll
    for (int nf = 0; nf < 8; nf++) {
        const int col = n0w + nf * 8 + 2 * tig;
        if (col < 64) {
            if (row0 < N_NODES) {
                float2 o = {acc[nf][0], acc[nf][1]};
                *reinterpret_cast<float2*>(g_t + (size_t)row0 * COUT + col) = o;
            }
            if (row1 < N_NODES) {
                float2 o = {acc[nf][2], acc[nf][3]};
                *reinterpret_cast<float2*>(g_t + (size_t)row1 * COUT + col) = o;
            }
        } else {
            const int cc = col - 64;
            const float bb0 = b2[cc], bb1 = b2[cc + 1];
            if (row0 < N_NODES) {
                float2 o = {acc[nf][0] + bb0, acc[nf][1] + bb1};
                *reinterpret_cast<float2*>(g_r + (size_t)row0 * COUT + cc) = o;
            }
            if (row1 < N_NODES) {
                float2 o = {acc[nf][2] + bb0, acc[nf][3] + bb1};
                *reinterpret_cast<float2*>(g_r + (size_t)row1 * COUT + cc) = o;
            }
        }
    }
}

// ---------------- launch ----------------
extern "C" void kernel_launch(void* const* d_in, const int* in_sizes, int n_in,
                              void* d_out, int out_size) {
    const float* x   = (const float*)d_in[0];
    const void*  ei  = d_in[1];
    const float* W1l = (const float*)d_in[2];
    const float* W1r = (const float*)d_in[3];
    const float* b1  = (const float*)d_in[4];
    const float* W2l = (const float*)d_in[5];
    const float* W2r = (const float*)d_in[6];
    const float* b2  = (const float*)d_in[7];
    float* out = (float*)d_out;

    const int E = in_sizes[1] / 2;

    {
        int blocks = (N_NODES + 255) / 256;
        zero_deg<<<blocks, 256>>>();
    }
    {
        long long n64_safe = (long long)E / 2;
        detect_kernel<<<1024, 256>>>((const long long*)ei, n64_safe);
    }
    {
        int blocks = (E + 255) / 256;
        decode_count<<<blocks, 256>>>(ei, E);
        block_sum_kernel<<<SCAN_BLOCKS, 256>>>();
        scan_bsum_kernel<<<1, 512>>>();
        block_scan_kernel<<<SCAN_BLOCKS, 256>>>();
        scatter_kernel<<<blocks, 256>>>(E);
    }
    {
        long long threads = (long long)N_NODES * 32;
        int blocks = (int)((threads + 255) / 256);
        agg1_csr<<<blocks, 256>>>(x);
    }
    {
        int blocks = (N_NODES + 63) / 64;
        gemm1_mma<<<blocks, 256>>>(x, W1l, W1r, b1);
        gemm2_mma<<<blocks, 256>>>(W2l, W2r, b2);
    }
    {
        long long threads = (long long)N_NODES * 32;
        int blocks = (int)((threads + 255) / 256);
        agg2_final<<<blocks, 256>>>(out);
    }
}